// round 11
// baseline (speedup 1.0000x reference)
#include <cuda_runtime.h>
#include <cuda_fp16.h>
#include <cstdint>
#include <math.h>

#define B_SZ 16384
#define N_SZ 1024
#define I_SZ 128
#define O_SZ 64
#define REFRACT 0.9f

#define BM 32
#define KC 64
#define NCHUNK 16
#define THREADS 128

// smem: A16 ring (2 x 4KB) @0 | B ring (3 x 8KB) @8192 | bias/act
#define OFF_A16 0
#define OFF_B   8192
#define OFF_BIAS 32768
#define OFF_ACT  33024
#define SMEM_TOTAL 33280

// Prepped weights, PRE-SWIZZLED per chunk: chunk c, row n, col kk ->
// byte offset c*8192 + swz(n*128 + kk*2). fp16, refractory folded, transposed.
__device__ __align__(16) unsigned short g_Wsw[O_SZ * N_SZ];
__device__ float g_bias[O_SZ];
__device__ int   g_act[O_SZ];

// ---------------- helpers ----------------
__device__ __forceinline__ uint32_t smem_u32(const void* p) {
    uint32_t a;
    asm("{ .reg .u64 t; cvta.to.shared.u64 t, %1; cvt.u32.u64 %0, t; }"
        : "=r"(a) : "l"(p));
    return a;
}
// packed f16x2: low half = f16(lo), high half = f16(hi)
__device__ __forceinline__ uint32_t pack_f16(float lo, float hi) {
    uint32_t r;
    asm("cvt.rn.f16x2.f32 %0, %1, %2;" : "=r"(r) : "f"(hi), "f"(lo));
    return r;
}
__device__ __forceinline__ uint32_t swz(uint32_t off) {
    return off ^ ((off >> 3) & 0x70);
}
__device__ __forceinline__ void ldsm4(uint32_t* r, uint32_t addr) {
    asm volatile("ldmatrix.sync.aligned.m8n8.x4.shared.b16 {%0,%1,%2,%3}, [%4];"
                 : "=r"(r[0]), "=r"(r[1]), "=r"(r[2]), "=r"(r[3]) : "r"(addr));
}
__device__ __forceinline__ void mma16816(float* c, const uint32_t* a,
                                         uint32_t b0, uint32_t b1) {
    asm volatile(
        "mma.sync.aligned.m16n8k16.row.col.f32.f16.f16.f32 "
        "{%0,%1,%2,%3}, {%4,%5,%6,%7}, {%8,%9}, {%0,%1,%2,%3};"
        : "+f"(c[0]), "+f"(c[1]), "+f"(c[2]), "+f"(c[3])
        : "r"(a[0]), "r"(a[1]), "r"(a[2]), "r"(a[3]), "r"(b0), "r"(b1));
}
__device__ __forceinline__ void cp_async16(uint32_t dst, const void* src) {
    asm volatile("cp.async.cg.shared.global [%0], [%1], 16;"
                 :: "r"(dst), "l"(src) : "memory");
}
#define CP_COMMIT() asm volatile("cp.async.commit_group;" ::: "memory")
#define CP_WAIT(n)  asm volatile("cp.async.wait_group %0;" :: "n"(n) : "memory")

__device__ __forceinline__ float activate(float x, int a) {
    if (a == 0) return fmaxf(x, 0.0f);
    if (a == 1) return tanhf(x);
    if (a == 2) return 1.0f / (1.0f + expf(-x));
    return x;
}

// ---------------- prep: fold refractory, transpose, fp16, pre-swizzle ----------------
__global__ void prep_kernel(const float* __restrict__ W,
                            const float* __restrict__ bias,
                            const int* __restrict__ act) {
    int idx = blockIdx.x * blockDim.x + threadIdx.x;   // 65536
    if (idx < O_SZ * N_SZ) {
        int k = idx >> 6;        // 0..1023
        int n = idx & 63;        // output col
        float s = (k >= I_SZ && k < (N_SZ - O_SZ)) ? REFRACT : 1.0f;
        float w = W[(size_t)k * N_SZ + (N_SZ - O_SZ) + n] * s;
        const int c = k >> 6, kk = k & 63;
        const uint32_t off = swz((uint32_t)(n * 128 + kk * 2));
        *(unsigned short*)((char*)g_Wsw + (size_t)c * 8192 + off) =
            __half_as_ushort(__float2half_rn(w));
    }
    if (idx < O_SZ) {
        g_bias[idx] = bias[(N_SZ - O_SZ) + idx];
        g_act[idx]  = act[(N_SZ - O_SZ) + idx];
    }
}

// ---------------- A chunk: gmem -> regs ----------------
// A: 32 rows x 64 f32; thread t -> row t>>2, 16 floats at (t&3)*16 (4 LDG.128)
__device__ __forceinline__ void load_A(int i, int t, int m0,
                                       const float* __restrict__ prev,
                                       const float* __restrict__ inp,
                                       float4 (&a)[4]) {
    const int k0 = i * KC;
    const int rr = t >> 2;
    const int kf = (t & 3) * 16;
    const float* s = (k0 < I_SZ)
        ? inp  + (size_t)(m0 + rr) * I_SZ + k0 + kf
        : prev + (size_t)(m0 + rr) * N_SZ + k0 + kf;
#pragma unroll
    for (int p = 0; p < 4; p++) a[p] = ((const float4*)s)[p];
}

// ---------------- A chunk: regs -> smem (fp16 convert + swizzle) ----------------
__device__ __forceinline__ void store_A(uint32_t base, int t, const float4 (&a)[4]) {
    const int row = t >> 2;
    const int u4  = t & 3;
    uint32_t h[8];
#pragma unroll
    for (int p = 0; p < 4; p++) {
        h[2 * p]     = pack_f16(a[p].x, a[p].y);
        h[2 * p + 1] = pack_f16(a[p].z, a[p].w);
    }
    const uint32_t o0 = base + swz((uint32_t)(row * 128 + u4 * 32));
    const uint32_t o1 = base + swz((uint32_t)(row * 128 + u4 * 32 + 16));
    asm volatile("st.shared.v4.b32 [%0], {%1,%2,%3,%4};"
                 :: "r"(o0), "r"(h[0]), "r"(h[1]), "r"(h[2]), "r"(h[3]) : "memory");
    asm volatile("st.shared.v4.b32 [%0], {%1,%2,%3,%4};"
                 :: "r"(o1), "r"(h[4]), "r"(h[5]), "r"(h[6]), "r"(h[7]) : "memory");
}

// ---------------- B chunk: cp.async from pre-swizzled weights ----------------
__device__ __forceinline__ void cp_B(int i, int t, uint32_t sbse) {
    const uint32_t dst = sbse + OFF_B + (uint32_t)((i % 3) * 8192) + (uint32_t)(t * 64);
    const char* src = (const char*)g_Wsw + (size_t)i * 8192 + (size_t)t * 64;
#pragma unroll
    for (int p = 0; p < 4; p++)
        cp_async16(dst + p * 16, src + p * 16);
}

// ---------------- main kernel ----------------
__global__ __launch_bounds__(THREADS, 4)
void mma_kernel(const float* __restrict__ prev,
                const float* __restrict__ inp,
                float* __restrict__ out) {
    extern __shared__ __align__(1024) char smem[];
    const uint32_t sbse = smem_u32(smem);
    const int t = threadIdx.x;
    const int lane = t & 31, wid = t >> 5;
    const int m0 = blockIdx.x * BM;

    if (t < O_SZ) {
        ((float*)(smem + OFF_BIAS))[t] = g_bias[t];
        ((int*)(smem + OFF_ACT))[t]    = g_act[t];
    }

    // warp tiling: 2 M-groups (16 rows) x 2 N-halves (32 cols)
    const int mg = wid >> 1, nh = wid & 1;
    const int lrow = lane & 7, seg = lane >> 3;
    const int arow = mg * 16 + lrow + ((seg & 1) << 3);
    const int akb0 = (seg & 2) << 3;
    const int browb = lrow + ((seg & 2) << 2);
    const int bkb0 = (seg & 1) << 4;

    float acc[4][4];
#pragma unroll
    for (int j = 0; j < 4; j++)
#pragma unroll
        for (int c = 0; c < 4; c++) acc[j][c] = 0.0f;

    float4 A[4];

    // prologue: B0,B1 in flight; A0 staged
    load_A(0, t, m0, prev, inp, A);
    cp_B(0, t, sbse);
    CP_COMMIT();
    cp_B(1, t, sbse);
    CP_COMMIT();
    store_A(sbse, t, A);
    CP_WAIT(1);               // B0 arrived (B1 may pend)
    __syncthreads();

    for (int i = 0; i < NCHUNK; i++) {
        if (i + 1 < NCHUNK) load_A(i + 1, t, m0, prev, inp, A);
        if (i + 2 < NCHUNK) {
            cp_B(i + 2, t, sbse);
            CP_COMMIT();
        }

        // compute chunk i
        const uint32_t stA = sbse + (uint32_t)((i & 1) * 4096);
        const uint32_t stB = sbse + OFF_B + (uint32_t)((i % 3) * 8192);
#pragma unroll
        for (int s = 0; s < 4; s++) {
            uint32_t av[4];
            ldsm4(av, stA + swz((uint32_t)(arow * 128 + s * 32 + akb0)));
#pragma unroll
            for (int jj = 0; jj < 2; jj++) {
                uint32_t bv[4];
                ldsm4(bv, stB +
                          swz((uint32_t)((nh * 32 + jj * 16 + browb) * 128 + s * 32 + bkb0)));
                mma16816(acc[2 * jj],     av, bv[0], bv[1]);
                mma16816(acc[2 * jj + 1], av, bv[2], bv[3]);
            }
        }

        if (i + 1 < NCHUNK)
            store_A(sbse + (uint32_t)(((i + 1) & 1) * 4096), t, A);
        if (i + 2 < NCHUNK) { CP_WAIT(1); }   // B(i+1) arrived, B(i+2) may pend
        else                { CP_WAIT(0); }   // tail: drain everything
        __syncthreads();
    }

    // ---------------- epilogue ----------------
    const float* sbias = (const float*)(smem + OFF_BIAS);
    const int*   sact  = (const int*)(smem + OFF_ACT);
    const int g = lane >> 2, q = lane & 3;
    const int row0 = m0 + mg * 16 + g;
#pragma unroll
    for (int j = 0; j < 4; j++) {
        const int col = nh * 32 + (j >> 1) * 16 + (j & 1) * 8 + q * 2;
        const float b0 = sbias[col], b1 = sbias[col + 1];
        const int   i0 = sact[col],  i1 = sact[col + 1];
        float2 v0, v1;
        v0.x = activate(acc[j][0] + b0, i0);
        v0.y = activate(acc[j][1] + b1, i1);
        v1.x = activate(acc[j][2] + b0, i0);
        v1.y = activate(acc[j][3] + b1, i1);
        *(float2*)(out + (size_t)row0 * O_SZ + col)       = v0;
        *(float2*)(out + (size_t)(row0 + 8) * O_SZ + col) = v1;
    }
}

extern "C" void kernel_launch(void* const* d_in, const int* in_sizes, int n_in,
                              void* d_out, int out_size) {
    const float* prev = (const float*)d_in[0];   // [16384,1024] f32
    const float* inp  = (const float*)d_in[1];   // [16384,128]  f32
    const float* W    = (const float*)d_in[2];   // [1024,1024]  f32
    const float* bias = (const float*)d_in[3];   // [1024]       f32
    const int*   act  = (const int*)d_in[4];     // [1024]       i32
    float* out = (float*)d_out;                  // [16384,64]   f32

    cudaFuncSetAttribute(mma_kernel,
                         cudaFuncAttributeMaxDynamicSharedMemorySize, SMEM_TOTAL);

    prep_kernel<<<(O_SZ * N_SZ + 255) / 256, 256>>>(W, bias, act);
    mma_kernel<<<B_SZ / BM, THREADS, SMEM_TOTAL>>>(prev, inp, out);
}

// round 12
// speedup vs baseline: 1.0623x; 1.0623x over previous
#include <cuda_runtime.h>
#include <cuda_fp16.h>
#include <cstdint>
#include <math.h>

#define B_SZ 16384
#define N_SZ 1024
#define I_SZ 128
#define O_SZ 64
#define REFRACT 0.9f

#define BM 64
#define KC 64
#define NCHUNK 16
#define THREADS 256

// smem layout:
//  A32 ring (3 x 16KB) @ 0        raw fp32 A chunks (cp.async)
//  B16 ring (4 x 8KB)  @ 49152    pre-swizzled fp16 W chunks (cp.async)
//  A16 ring (2 x 8KB)  @ 81920    converted fp16 A tiles
#define OFF_A32 0
#define OFF_B   49152
#define OFF_A16 81920
#define OFF_BIAS 98304
#define OFF_ACT  98560
#define SMEM_TOTAL 98816

// Prepped weights, PRE-SWIZZLED per chunk: chunk c, row n, col kk ->
// byte offset c*8192 + swz(n*128 + kk*2). fp16, refractory folded, transposed.
__device__ __align__(16) unsigned short g_Wsw[O_SZ * N_SZ];
__device__ float g_bias[O_SZ];
__device__ int   g_act[O_SZ];

// ---------------- helpers ----------------
__device__ __forceinline__ uint32_t smem_u32(const void* p) {
    uint32_t a;
    asm("{ .reg .u64 t; cvta.to.shared.u64 t, %1; cvt.u32.u64 %0, t; }"
        : "=r"(a) : "l"(p));
    return a;
}
// packed f16x2: low half = f16(lo), high half = f16(hi)
__device__ __forceinline__ uint32_t pack_f16(float lo, float hi) {
    uint32_t r;
    asm("cvt.rn.f16x2.f32 %0, %1, %2;" : "=r"(r) : "f"(hi), "f"(lo));
    return r;
}
__device__ __forceinline__ uint32_t swz(uint32_t off) {
    return off ^ ((off >> 3) & 0x70);
}
__device__ __forceinline__ void ldsm4(uint32_t* r, uint32_t addr) {
    asm volatile("ldmatrix.sync.aligned.m8n8.x4.shared.b16 {%0,%1,%2,%3}, [%4];"
                 : "=r"(r[0]), "=r"(r[1]), "=r"(r[2]), "=r"(r[3]) : "r"(addr));
}
__device__ __forceinline__ void mma16816(float* c, const uint32_t* a,
                                         uint32_t b0, uint32_t b1) {
    asm volatile(
        "mma.sync.aligned.m16n8k16.row.col.f32.f16.f16.f32 "
        "{%0,%1,%2,%3}, {%4,%5,%6,%7}, {%8,%9}, {%0,%1,%2,%3};"
        : "+f"(c[0]), "+f"(c[1]), "+f"(c[2]), "+f"(c[3])
        : "r"(a[0]), "r"(a[1]), "r"(a[2]), "r"(a[3]), "r"(b0), "r"(b1));
}
__device__ __forceinline__ void cp_async16(uint32_t dst, const void* src) {
    asm volatile("cp.async.cg.shared.global [%0], [%1], 16;"
                 :: "r"(dst), "l"(src) : "memory");
}
#define CP_COMMIT() asm volatile("cp.async.commit_group;" ::: "memory")
#define CP_WAIT(n)  asm volatile("cp.async.wait_group %0;" :: "n"(n) : "memory")

__device__ __forceinline__ float activate(float x, int a) {
    if (a == 0) return fmaxf(x, 0.0f);
    if (a == 1) return tanhf(x);
    if (a == 2) return 1.0f / (1.0f + expf(-x));
    return x;
}

// ---------------- prep: fold refractory, transpose, fp16, pre-swizzle ----------------
__global__ void prep_kernel(const float* __restrict__ W,
                            const float* __restrict__ bias,
                            const int* __restrict__ act) {
    int idx = blockIdx.x * blockDim.x + threadIdx.x;   // 65536
    if (idx < O_SZ * N_SZ) {
        int k = idx >> 6;        // 0..1023
        int n = idx & 63;        // output col
        float s = (k >= I_SZ && k < (N_SZ - O_SZ)) ? REFRACT : 1.0f;
        float w = W[(size_t)k * N_SZ + (N_SZ - O_SZ) + n] * s;
        const int c = k >> 6, kk = k & 63;
        const uint32_t off = swz((uint32_t)(n * 128 + kk * 2));
        *(unsigned short*)((char*)g_Wsw + (size_t)c * 8192 + off) =
            __half_as_ushort(__float2half_rn(w));
    }
    if (idx < O_SZ) {
        g_bias[idx] = bias[(N_SZ - O_SZ) + idx];
        g_act[idx]  = act[(N_SZ - O_SZ) + idx];
    }
}

// ---------------- chunk i: issue all cp.async (A fp32 + B pre-swizzled) ----------------
__device__ __forceinline__ void cp_chunk(int i, int t, int m0, uint32_t sbse,
                                         const float* __restrict__ prev,
                                         const float* __restrict__ inp) {
    const int k0 = i * KC;
    const int r  = t >> 2;
    const int c4 = (t & 3) * 16;       // float col within chunk
    const float* src = (k0 < I_SZ)
        ? inp  + (size_t)(m0 + r) * I_SZ + k0 + c4
        : prev + (size_t)(m0 + r) * N_SZ + k0 + c4;
    const uint32_t a32 = sbse + OFF_A32 + (uint32_t)((i % 3) * 16384)
                       + (uint32_t)(r * 256 + (t & 3) * 64);
#pragma unroll
    for (int p = 0; p < 4; p++)
        cp_async16(a32 + p * 16, src + p * 4);

    const uint32_t bdst = sbse + OFF_B + (uint32_t)((i & 3) * 8192);
    const char* bs = (const char*)g_Wsw + (size_t)i * 8192;
    cp_async16(bdst + t * 16,        bs + (size_t)t * 16);
    cp_async16(bdst + 4096 + t * 16, bs + 4096 + (size_t)t * 16);
}

// ---------------- convert chunk j: A32 smem -> A16 smem (fp16 + swizzle) ----------------
__device__ __forceinline__ void convert_A(int j, int t, char* smem, uint32_t sbse) {
    const char* a32 = smem + OFF_A32 + (j % 3) * 16384;
    const int row = t >> 2;
    const int u4  = t & 3;
    float4 a[4];
#pragma unroll
    for (int p = 0; p < 4; p++)
        a[p] = *(const float4*)(a32 + row * 256 + u4 * 64 + p * 16);
    uint32_t h[8];
#pragma unroll
    for (int p = 0; p < 4; p++) {
        h[2 * p]     = pack_f16(a[p].x, a[p].y);
        h[2 * p + 1] = pack_f16(a[p].z, a[p].w);
    }
    const uint32_t base = sbse + OFF_A16 + (uint32_t)((j & 1) * 8192);
    const uint32_t o0 = base + swz((uint32_t)(row * 128 + u4 * 32));
    const uint32_t o1 = base + swz((uint32_t)(row * 128 + u4 * 32 + 16));
    asm volatile("st.shared.v4.b32 [%0], {%1,%2,%3,%4};"
                 :: "r"(o0), "r"(h[0]), "r"(h[1]), "r"(h[2]), "r"(h[3]) : "memory");
    asm volatile("st.shared.v4.b32 [%0], {%1,%2,%3,%4};"
                 :: "r"(o1), "r"(h[4]), "r"(h[5]), "r"(h[6]), "r"(h[7]) : "memory");
}

// ---------------- main kernel ----------------
__global__ __launch_bounds__(THREADS, 2)
void mma_kernel(const float* __restrict__ prev,
                const float* __restrict__ inp,
                float* __restrict__ out) {
    extern __shared__ __align__(1024) char smem[];
    const uint32_t sbse = smem_u32(smem);
    const int t = threadIdx.x;
    const int lane = t & 31, wid = t >> 5;
    const int m0 = blockIdx.x * BM;

    if (t < O_SZ) {
        ((float*)(smem + OFF_BIAS))[t] = g_bias[t];
        ((int*)(smem + OFF_ACT))[t]    = g_act[t];
    }

    // warp tiling: 4 M-groups (16 rows) x 2 N-halves (32 cols)
    const int mg = wid >> 1, nh = wid & 1;
    const int lrow = lane & 7, seg = lane >> 3;
    const int arow = mg * 16 + lrow + ((seg & 1) << 3);
    const int akb0 = (seg & 2) << 3;
    const int browb = lrow + ((seg & 2) << 2);
    const int bkb0 = (seg & 1) << 4;

    float acc[4][4];
#pragma unroll
    for (int j = 0; j < 4; j++)
#pragma unroll
        for (int c = 0; c < 4; c++) acc[j][c] = 0.0f;

    // prologue: chunks 0,1,2 in flight as separate groups
    cp_chunk(0, t, m0, sbse, prev, inp);
    CP_COMMIT();
    cp_chunk(1, t, m0, sbse, prev, inp);
    CP_COMMIT();
    cp_chunk(2, t, m0, sbse, prev, inp);
    CP_COMMIT();
    CP_WAIT(2);               // chunk 0 arrived; 1,2 still pending
    __syncthreads();
    convert_A(0, t, smem, sbse);

    for (int i = 0; i < NCHUNK; i++) {
        // ensure chunk i+1 arrived; keep later chunks in flight
        if (i + 3 < NCHUNK) { CP_WAIT(1); }
        else                { CP_WAIT(0); }
        __syncthreads();      // data visible to all; prior compute/convert done

        if (i + 3 < NCHUNK) {
            cp_chunk(i + 3, t, m0, sbse, prev, inp);
            CP_COMMIT();
        }
        if (i + 1 < NCHUNK)
            convert_A(i + 1, t, smem, sbse);

        // compute chunk i
        const uint32_t stA = sbse + OFF_A16 + (uint32_t)((i & 1) * 8192);
        const uint32_t stB = sbse + OFF_B   + (uint32_t)((i & 3) * 8192);
#pragma unroll
        for (int s = 0; s < 4; s++) {
            uint32_t av[4];
            ldsm4(av, stA + swz((uint32_t)(arow * 128 + s * 32 + akb0)));
#pragma unroll
            for (int jj = 0; jj < 2; jj++) {
                uint32_t bv[4];
                ldsm4(bv, stB +
                          swz((uint32_t)((nh * 32 + jj * 16 + browb) * 128 + s * 32 + bkb0)));
                mma16816(acc[2 * jj],     av, bv[0], bv[1]);
                mma16816(acc[2 * jj + 1], av, bv[2], bv[3]);
            }
        }
    }

    // ---------------- epilogue ----------------
    const float* sbias = (const float*)(smem + OFF_BIAS);
    const int*   sact  = (const int*)(smem + OFF_ACT);
    const int g = lane >> 2, q = lane & 3;
    const int row0 = m0 + mg * 16 + g;
#pragma unroll
    for (int j = 0; j < 4; j++) {
        const int col = nh * 32 + (j >> 1) * 16 + (j & 1) * 8 + q * 2;
        const float b0 = sbias[col], b1 = sbias[col + 1];
        const int   i0 = sact[col],  i1 = sact[col + 1];
        float2 v0, v1;
        v0.x = activate(acc[j][0] + b0, i0);
        v0.y = activate(acc[j][1] + b1, i1);
        v1.x = activate(acc[j][2] + b0, i0);
        v1.y = activate(acc[j][3] + b1, i1);
        *(float2*)(out + (size_t)row0 * O_SZ + col)       = v0;
        *(float2*)(out + (size_t)(row0 + 8) * O_SZ + col) = v1;
    }
}

extern "C" void kernel_launch(void* const* d_in, const int* in_sizes, int n_in,
                              void* d_out, int out_size) {
    const float* prev = (const float*)d_in[0];   // [16384,1024] f32
    const float* inp  = (const float*)d_in[1];   // [16384,128]  f32
    const float* W    = (const float*)d_in[2];   // [1024,1024]  f32
    const float* bias = (const float*)d_in[3];   // [1024]       f32
    const int*   act  = (const int*)d_in[4];     // [1024]       i32
    float* out = (float*)d_out;                  // [16384,64]   f32

    cudaFuncSetAttribute(mma_kernel,
                         cudaFuncAttributeMaxDynamicSharedMemorySize, SMEM_TOTAL);

    prep_kernel<<<(O_SZ * N_SZ + 255) / 256, 256>>>(W, bias, act);
    mma_kernel<<<B_SZ / BM, THREADS, SMEM_TOTAL>>>(prev, inp, out);
}